// round 12
// baseline (speedup 1.0000x reference)
#include <cuda_runtime.h>
#include <cuda_bf16.h>
#include <cstdint>

#define B_  64
#define C_  256
#define Wn_ 256
#define E_  2048
#define D_  2048

#define KT     64            // bf16 K per stage (128B rows, SW128)
#define KSTEPS (E_/KT)       // 32
#define NCH2   8             // n-chunks of 256 cols per CTA (covers D)
#define KQ_    8             // leader GEMM K-splits
#define KSL    (E_/KQ_/KT)   // 4 k-steps per leader CTA

// ---------------- scratch ----------------
__device__ int   g_idx[B_];
__device__ float g_leader[B_*D_];
__device__ float g_leadp[KQ_][B_*D_];
__device__ float g_dot[B_*Wn_];
__device__ float g_nrm[B_*Wn_];
__device__ __nv_bfloat16 g_xt16[(size_t)B_*Wn_*E_];   // 64 MB
__device__ __nv_bfloat16 g_w16[(size_t)D_*E_];        //  8 MB
__device__ __nv_bfloat16 g_wi16[(size_t)D_*E_];       //  8 MB
__device__ __nv_bfloat16 g_xl16[(size_t)B_*E_];       // 256 KB

// ---------------- helpers ----------------
__device__ __forceinline__ uint32_t swz(uint32_t o){ return o ^ ((o>>3)&0x70); }

__device__ __forceinline__ void cpasync16(uint32_t s, const void* g){
  asm volatile("cp.async.cg.shared.global [%0],[%1],16;"::"r"(s),"l"(g));
}
__device__ __forceinline__ void cpcommit(){ asm volatile("cp.async.commit_group;"); }
__device__ __forceinline__ void cpwait0(){ asm volatile("cp.async.wait_group 0;"); }

__device__ __forceinline__ void cp_mbar_arrive(uint32_t mb){
  asm volatile("cp.async.mbarrier.arrive.noinc.shared.b64 [%0];" :: "r"(mb) : "memory");
}
__device__ __forceinline__ void mbar_arrive(uint32_t mb){
  asm volatile("mbarrier.arrive.shared.b64 _, [%0];" :: "r"(mb) : "memory");
}
__device__ __forceinline__ void mbar_init(uint32_t mb, uint32_t cnt){
  asm volatile("mbarrier.init.shared.b64 [%0], %1;" :: "r"(mb), "r"(cnt) : "memory");
}
__device__ __forceinline__ void mbar_wait(uint32_t mb, uint32_t parity){
  uint32_t done;
  asm volatile(
    "{\n\t.reg .pred p;\n\t"
    "mbarrier.try_wait.parity.acquire.cta.shared::cta.b64 p, [%1], %2;\n\t"
    "selp.b32 %0, 1, 0, p;\n\t}"
    : "=r"(done) : "r"(mb), "r"(parity) : "memory");
  if (!done){
    asm volatile(
      "{\n\t.reg .pred P1;\n\t"
      "WL_%=:\n\t"
      "mbarrier.try_wait.parity.acquire.cta.shared::cta.b64 P1, [%0], %1, 0x989680;\n\t"
      "@P1 bra.uni WD_%=;\n\t"
      "bra.uni WL_%=;\n\t"
      "WD_%=:\n\t}"
      :: "r"(mb), "r"(parity) : "memory");
  }
}

__device__ __forceinline__ void ldsm4(uint32_t* r, uint32_t a){
  asm volatile("ldmatrix.sync.aligned.m8n8.x4.shared.b16 {%0,%1,%2,%3},[%4];"
   :"=r"(r[0]),"=r"(r[1]),"=r"(r[2]),"=r"(r[3]):"r"(a));
}
__device__ __forceinline__ void mma16816(float* c, const uint32_t* a, const uint32_t* b){
  asm volatile("mma.sync.aligned.m16n8k16.row.col.f32.bf16.bf16.f32 "
   "{%0,%1,%2,%3},{%4,%5,%6,%7},{%8,%9},{%0,%1,%2,%3};"
   :"+f"(c[0]),"+f"(c[1]),"+f"(c[2]),"+f"(c[3])
   :"r"(a[0]),"r"(a[1]),"r"(a[2]),"r"(a[3]),"r"(b[0]),"r"(b[1]));
}

// ---------------- kernel 1: argmax ----------------
__global__ void k_argmax(const float* __restrict__ y){
  int b = blockIdx.x, t = threadIdx.x;
  __shared__ float vs[256]; __shared__ int is[256];
  vs[t] = y[b*C_ + t]; is[t] = t; __syncthreads();
  for (int s=128; s>0; s>>=1){
    if (t < s){
      float v2 = vs[t+s]; int i2 = is[t+s];
      if (v2 > vs[t] || (v2 == vs[t] && i2 < is[t])) { vs[t]=v2; is[t]=i2; }
    }
    __syncthreads();
  }
  if (t==0) g_idx[b] = is[0];
}

// ---------------- kernel 2: gather leader inputs -> bf16 ----------------
__global__ void k_gather(const float* __restrict__ x_img){
  int b = blockIdx.x, t = threadIdx.x;
  int idx = g_idx[b];
  const float4* src = (const float4*)(x_img + ((size_t)b*C_ + idx)*E_);
  __nv_bfloat162* dst = (__nv_bfloat162*)(g_xl16 + (size_t)b*E_);
  for (int i=t; i<E_/4; i+=256){
    float4 v = src[i];
    dst[i*2+0] = __floats2bfloat162_rn(v.x, v.y);
    dst[i*2+1] = __floats2bfloat162_rn(v.z, v.w);
  }
}

// ---------------- kernel 3: fp32 -> bf16 bulk convert ----------------
__global__ void k_convert(const float* __restrict__ xt, const float* __restrict__ Ww,
                          const float* __restrict__ Wi){
  const long NX4  = (long)B_*Wn_*E_/4;
  const long NW4  = (long)D_*E_/4;
  long i = (long)blockIdx.x*blockDim.x + threadIdx.x;
  long stride = (long)gridDim.x*blockDim.x;
  for (; i < NX4 + 2*NW4; i += stride){
    const float4* src; __nv_bfloat16* dst; long j;
    if (i < NX4)          { src=(const float4*)xt; dst=g_xt16; j=i; }
    else if (i < NX4+NW4) { src=(const float4*)Ww; dst=g_w16;  j=i-NX4; }
    else                  { src=(const float4*)Wi; dst=g_wi16; j=i-NX4-NW4; }
    float4 v = src[j];
    __nv_bfloat162* d2 = (__nv_bfloat162*)(dst + j*4);
    d2[0] = __floats2bfloat162_rn(v.x, v.y);
    d2[1] = __floats2bfloat162_rn(v.z, v.w);
  }
}

// ---------------- kernel 4: leader GEMM, split-K (bf16 mma.sync) ----------------
__global__ void __launch_bounds__(256) k_leadmma(){
  __shared__ __align__(1024) char sm[49152];
  const int t = threadIdx.x, dt = blockIdx.x, kq = blockIdx.y;
  const int w = t>>5, l = t&31;
  const int wm = w>>2, wn = w&3;
  uint32_t sb = (uint32_t)__cvta_generic_to_shared(sm);

  const __nv_bfloat16* Abase = g_xl16 + (size_t)kq*(E_/KQ_);
  const __nv_bfloat16* Bbase = g_wi16 + (size_t)dt*128*E_ + (size_t)kq*(E_/KQ_);

  float c[2][4][4];
  #pragma unroll
  for (int i=0;i<2;i++) for (int j=0;j<4;j++) for (int e=0;e<4;e++) c[i][j][e]=0.f;

  {
    int u = t; int row=u>>3, seg=u&7;
    cpasync16(sb + 0 + swz(row*128+seg*16), Abase + (size_t)row*E_ + seg*8);
    u = t+256; row=u>>3; seg=u&7;
    cpasync16(sb + 0 + swz(row*128+seg*16), Abase + (size_t)row*E_ + seg*8);
    #pragma unroll
    for (int i=0;i<4;i++){ int v = t+256*i; int r2=v>>3, s2=v&7;
      cpasync16(sb + 16384 + swz(r2*128+s2*16), Bbase + (size_t)r2*E_ + s2*8); }
    cpcommit();
  }
  const uint32_t aRow = (uint32_t)(32*wm + (l&15));
  const uint32_t aSeg = (uint32_t)((l>>4)&1);
  const uint32_t bR4  = (uint32_t)(32*wn + (l&7) + 8*((l>>4)&1));
  const uint32_t bS4  = (uint32_t)((l>>3)&1);

  for (int ks=0; ks<KSL; ks++){
    cpwait0(); __syncthreads();
    if (ks+1 < KSL){
      int p = (ks+1)&1;
      int u=t, row=u>>3, seg=u&7;
      cpasync16(sb + p*8192 + swz(row*128+seg*16), Abase + (size_t)row*E_ + (size_t)(ks+1)*KT + seg*8);
      u=t+256; row=u>>3; seg=u&7;
      cpasync16(sb + p*8192 + swz(row*128+seg*16), Abase + (size_t)row*E_ + (size_t)(ks+1)*KT + seg*8);
      #pragma unroll
      for (int i=0;i<4;i++){ int v=t+256*i; int r2=v>>3, s2=v&7;
        cpasync16(sb + 16384 + p*16384 + swz(r2*128+s2*16),
                  Bbase + (size_t)r2*E_ + (size_t)(ks+1)*KT + s2*8); }
      cpcommit();
    }
    uint32_t ab = sb + (ks&1)*8192;
    uint32_t bb = sb + 16384 + (ks&1)*16384;
    #pragma unroll
    for (int kk=0; kk<KT/16; kk++){
      uint32_t a[2][4], bf4[2][4];
      #pragma unroll
      for (int im=0;im<2;im++)
        ldsm4(a[im], ab + swz((aRow + 16*im)*128 + (kk*16 + aSeg*8)*2));
      #pragma unroll
      for (int pr=0;pr<2;pr++)
        ldsm4(bf4[pr], bb + swz((bR4 + 16*pr)*128 + (kk*16 + bS4*8)*2));
      #pragma unroll
      for (int im=0;im<2;im++)
        #pragma unroll
        for (int pr=0;pr<2;pr++){
          mma16816(c[im][2*pr],   a[im], &bf4[pr][0]);
          mma16816(c[im][2*pr+1], a[im], &bf4[pr][2]);
        }
    }
    __syncthreads();
  }
  float* outp = g_leadp[kq];
  #pragma unroll
  for (int im=0;im<2;im++)
    #pragma unroll
    for (int in_=0;in_<4;in_++)
      #pragma unroll
      for (int e=0;e<4;e++){
        int row = 32*wm + 16*im + (l>>2) + 8*(e>>1);
        int col = 32*wn + 8*in_ + 2*(l&3) + (e&1);
        outp[row*D_ + dt*128 + col] = c[im][in_][e];
      }
}

// ---------------- kernel 4b: merge leader partials + bias ----------------
__global__ void k_leadmerge(const float* __restrict__ bimg){
  int b = blockIdx.x, t = threadIdx.x;
  for (int d = t; d < D_; d += 256){
    int o = b*D_ + d;
    float s = bimg[d];
    #pragma unroll
    for (int q=0;q<KQ_;q++) s += g_leadp[q][o];
    g_leader[o] = s;
  }
}

// ---------------- kernel 5: fused words-GEMM (HMMA, big-N tiles) ----------------
// grid (2, 64) = (wtile, b). 256 thr, 8 warps as 2(M)x4(N), warp tile 64x64.
// CTA tile 128M x 256N per n-chunk, 8 n-chunks. 3-stage mbarrier ring (R6 protocol).
#define SM_STG  49152      // per-stage: A 16KB @+0, B 32KB @+16384
#define SM_BIAS 147456     // 256 f
#define SM_LEAD 148480     // 256 f
#define SM_RD   149504     // 512 f
#define SM_RN   151552     // 512 f
#define SM_MBAR 153600     // full[3] @ +0, empty[3] @ +24
#define SMEM_TOTAL 153664

__global__ void __launch_bounds__(256,1) k_main(const float* __restrict__ bwords){
  extern __shared__ __align__(1024) char smem[];
  const int t = threadIdx.x;
  const int wt = blockIdx.x, b = blockIdx.y;
  const int w = t>>5, l = t&31;
  const int wm = w>>2, wn = w&3;
  const int gid = l>>2, qid = l&3;
  uint32_t sbase = (uint32_t)__cvta_generic_to_shared(smem);
  float* bias_s = (float*)(smem + SM_BIAS);
  float* lead_s = (float*)(smem + SM_LEAD);
  float* red_d  = (float*)(smem + SM_RD);
  float* red_n  = (float*)(smem + SM_RN);
  const uint32_t mb_full  = sbase + SM_MBAR;
  const uint32_t mb_empty = sbase + SM_MBAR + 24;

  if (t == 0){
    #pragma unroll
    for (int i=0;i<3;i++){ mbar_init(mb_full + i*8, 256); mbar_init(mb_empty + i*8, 256); }
  }
  __syncthreads();

  const __nv_bfloat16* Abase = g_xt16 + ((size_t)(b*Wn_ + wt*128))*E_;

  // per-thread producer offsets: A 4 chunks (rows 0..127), B 8 chunks (rows 0..255)
  uint32_t aSmA[4], gOffA[4], aSmB[8], gOffB[8];
  #pragma unroll
  for (int i=0;i<4;i++){
    int u = t + 256*i; int row = u>>3, seg = u&7;
    aSmA[i]  = sbase + swz((uint32_t)(row*128 + seg*16));
    gOffA[i] = (uint32_t)(row*E_ + seg*8);
  }
  #pragma unroll
  for (int i=0;i<8;i++){
    int u = t + 256*i; int row = u>>3, seg = u&7;
    aSmB[i]  = sbase + 16384u + swz((uint32_t)(row*128 + seg*16));
    gOffB[i] = (uint32_t)(row*E_ + seg*8);
  }

  // prologue: produce stages 0,1
  #pragma unroll
  for (int gp=0; gp<2; gp++){
    const __nv_bfloat16* Ap = Abase + gp*KT;
    const __nv_bfloat16* Bp = g_w16 + gp*KT;   // nc=0
    #pragma unroll
    for (int i=0;i<4;i++) cpasync16(aSmA[i] + (uint32_t)(gp*SM_STG), Ap + gOffA[i]);
    #pragma unroll
    for (int i=0;i<8;i++) cpasync16(aSmB[i] + (uint32_t)(gp*SM_STG), Bp + gOffB[i]);
    cp_mbar_arrive(mb_full + gp*8);
  }

  const uint32_t aRow = (uint32_t)(64*wm + (l&15));
  const uint32_t aSeg = (uint32_t)((l>>4)&1);
  const uint32_t bR4  = (uint32_t)(64*wn + (l&7) + 8*((l>>4)&1));
  const uint32_t bS4  = (uint32_t)((l>>3)&1);

  float dot_tot = 0.f, nrm_tot = 0.f;
  float c[4][8][4];   // 128 accumulators: 4 m16 x 8 n8

  int sP = 2, pPw = 1;   // produce cursor (slot, parity-to-wait on empty)
  int sC = 0, pC = 0;    // consume cursor (slot, parity-to-wait on full)

  for (int nc=0; nc<NCH2; nc++){
    #pragma unroll
    for (int i=0;i<4;i++)
      #pragma unroll
      for (int j=0;j<8;j++)
        #pragma unroll
        for (int e=0;e<4;e++) c[i][j][e]=0.f;

    for (int ks=0; ks<KSTEPS; ks++){
      const int gs = nc*KSTEPS + ks;
      // produce stage gs+2
      if (gs+2 < NCH2*KSTEPS){
        mbar_wait(mb_empty + sP*8, (uint32_t)pPw);
        const int gp = gs+2, ksP = gp & (KSTEPS-1), ncP = gp >> 5;
        const __nv_bfloat16* Ap = Abase + ksP*KT;
        const __nv_bfloat16* Bp = g_w16 + (size_t)(ncP*256)*E_ + ksP*KT;
        const uint32_t so = (uint32_t)(sP*SM_STG);
        #pragma unroll
        for (int i=0;i<4;i++) cpasync16(aSmA[i] + so, Ap + gOffA[i]);
        #pragma unroll
        for (int i=0;i<8;i++) cpasync16(aSmB[i] + so, Bp + gOffB[i]);
        cp_mbar_arrive(mb_full + sP*8);
        if (++sP == 3){ sP = 0; pPw ^= 1; }
      }
      // consume stage gs
      mbar_wait(mb_full + sC*8, (uint32_t)pC);
      {
        uint32_t abuf = sbase + (uint32_t)(sC*SM_STG);
        uint32_t bbuf = abuf + 16384u;
        #pragma unroll
        for (int kk=0; kk<KT/16; kk++){
          uint32_t a[4][4], bf4[4][4];
          #pragma unroll
          for (int im=0;im<4;im++)
            ldsm4(a[im], abuf + swz((aRow + 16*im)*128 + (kk*16 + aSeg*8)*2));
          #pragma unroll
          for (int jp=0;jp<4;jp++)
            ldsm4(bf4[jp], bbuf + swz((bR4 + 16*jp)*128 + (kk*16 + bS4*8)*2));
          #pragma unroll
          for (int im=0;im<4;im++)
            #pragma unroll
            for (int jp=0;jp<4;jp++){
              mma16816(c[im][2*jp],   a[im], &bf4[jp][0]);
              mma16816(c[im][2*jp+1], a[im], &bf4[jp][2]);
            }
        }
      }
      mbar_arrive(mb_empty + sC*8);
      if (++sC == 3){ sC = 0; pC ^= 1; }
    }

    // ---- epilogue for this 256-col n-chunk ----
    __syncthreads();
    bias_s[t] = bwords[nc*256 + t];
    lead_s[t] = g_leader[b*D_ + nc*256 + t];
    __syncthreads();

    float dp[8], np2[8];
    #pragma unroll
    for (int s=0;s<8;s++){ dp[s]=0.f; np2[s]=0.f; }
    #pragma unroll
    for (int im=0;im<4;im++)
      #pragma unroll
      for (int jn=0;jn<8;jn++)
        #pragma unroll
        for (int e=0;e<4;e++){
          int col = 64*wn + 8*jn + 2*qid + (e&1);
          float v = c[im][jn][e] + bias_s[col];
          int s = im*2 + (e>>1);
          dp[s]  += v * lead_s[col];
          np2[s] += v * v;
        }
    #pragma unroll
    for (int s=0;s<8;s++){
      dp[s]  += __shfl_xor_sync(0xffffffffu, dp[s], 1);
      dp[s]  += __shfl_xor_sync(0xffffffffu, dp[s], 2);
      np2[s] += __shfl_xor_sync(0xffffffffu, np2[s], 1);
      np2[s] += __shfl_xor_sync(0xffffffffu, np2[s], 2);
    }
    if (qid == 0){
      #pragma unroll
      for (int s=0;s<8;s++){
        int r = 64*wm + 16*(s>>1) + gid + 8*(s&1);
        red_d[wn*128 + r] = dp[s];
        red_n[wn*128 + r] = np2[s];
      }
    }
    __syncthreads();
    if (t < 128){
      float ds=0.f, ns=0.f;
      #pragma unroll
      for (int q=0;q<4;q++){ ds += red_d[q*128+t]; ns += red_n[q*128+t]; }
      dot_tot += ds; nrm_tot += ns;
    }
    __syncthreads();
  }

  if (t < 128){
    int o = b*Wn_ + wt*128 + t;
    g_dot[o] = dot_tot;
    g_nrm[o] = nrm_tot;
  }
}

// ---------------- kernel 6: cosine + softmax ----------------
__global__ void k_final(float* __restrict__ out){
  int b = blockIdx.x, t = threadIdx.x;
  __shared__ float sh[256];
  float s = 0.f;
  const float* lr = g_leader + b*D_;
  for (int i=t; i<D_; i+=256){ float v = lr[i]; s += v*v; }
  sh[t] = s; __syncthreads();
  for (int st=128; st>0; st>>=1){ if (t<st) sh[t]+=sh[t+st]; __syncthreads(); }
  float ln = sqrtf(sh[0]);
  __syncthreads();

  int o = b*Wn_ + t;
  float dot = g_dot[o];
  float nr  = sqrtf(g_nrm[o]);
  float logit = dot / fmaxf(ln*nr, 1e-8f);

  sh[t] = logit; __syncthreads();
  for (int st=128; st>0; st>>=1){ if (t<st) sh[t]=fmaxf(sh[t],sh[t+st]); __syncthreads(); }
  float mx = sh[0]; __syncthreads();
  float ex = expf(logit - mx);
  sh[t] = ex; __syncthreads();
  for (int st=128; st>0; st>>=1){ if (t<st) sh[t]+=sh[t+st]; __syncthreads(); }
  out[b*Wn_ + t] = ex / sh[0];
}

// ---------------- launcher ----------------
extern "C" void kernel_launch(void* const* d_in, const int* in_sizes, int n_in,
                              void* d_out, int out_size){
  const float* x_img = (const float*)d_in[0];
  const float* x_txt = (const float*)d_in[1];
  const float* y     = (const float*)d_in[2];
  const float* Wimg  = (const float*)d_in[3];
  const float* bimg  = (const float*)d_in[4];
  const float* Ww    = (const float*)d_in[5];
  const float* bw    = (const float*)d_in[6];
  float* out = (float*)d_out;

  cudaFuncSetAttribute(k_main, cudaFuncAttributeMaxDynamicSharedMemorySize, SMEM_TOTAL);

  k_argmax<<<B_, 256>>>(y);
  k_gather<<<B_, 256>>>(x_img);
  k_convert<<<2048, 256>>>(x_txt, Ww, Wimg);
  k_leadmma<<<dim3(D_/128, KQ_), 256>>>();
  k_leadmerge<<<B_, 256>>>(bimg);
  k_main<<<dim3(2, B_), 256, SMEM_TOTAL>>>(bw);
  k_final<<<B_, 256>>>(out);
}

// round 13
// speedup vs baseline: 1.4197x; 1.4197x over previous
#include <cuda_runtime.h>
#include <cuda_bf16.h>
#include <cstdint>

#define B_  64
#define C_  256
#define Wn_ 256
#define E_  2048
#define D_  2048

#define KT     64            // bf16 K per stage (128B rows, SW128)
#define KSTEPS (E_/KT)       // 32
#define NCHP   8             // n-chunks (of 128 cols) per CTA; 2 CTAs cover D
#define KQ_    8             // leader GEMM K-splits
#define KSL    (E_/KQ_/KT)   // 4 k-steps per leader CTA

// ---------------- scratch ----------------
__device__ int   g_idx[B_];
__device__ float g_leader[B_*D_];
__device__ float g_leadp[KQ_][B_*D_];
__device__ float g_dotp[2][B_*Wn_];
__device__ float g_nrmp[2][B_*Wn_];
__device__ __nv_bfloat16 g_xt16[(size_t)B_*Wn_*E_];   // 64 MB
__device__ __nv_bfloat16 g_w16[(size_t)D_*E_];        //  8 MB
__device__ __nv_bfloat16 g_wi16[(size_t)D_*E_];       //  8 MB
__device__ __nv_bfloat16 g_xl16[(size_t)B_*E_];       // 256 KB

// ---------------- helpers ----------------
__device__ __forceinline__ uint32_t swz(uint32_t o){ return o ^ ((o>>3)&0x70); }

__device__ __forceinline__ void cpasync16(uint32_t s, const void* g){
  asm volatile("cp.async.cg.shared.global [%0],[%1],16;"::"r"(s),"l"(g));
}
__device__ __forceinline__ void cpcommit(){ asm volatile("cp.async.commit_group;"); }
__device__ __forceinline__ void cpwait0(){ asm volatile("cp.async.wait_group 0;"); }

__device__ __forceinline__ void cp_mbar_arrive(uint32_t mb){
  asm volatile("cp.async.mbarrier.arrive.noinc.shared.b64 [%0];" :: "r"(mb) : "memory");
}
__device__ __forceinline__ void mbar_arrive(uint32_t mb){
  asm volatile("mbarrier.arrive.shared.b64 _, [%0];" :: "r"(mb) : "memory");
}
__device__ __forceinline__ void mbar_init(uint32_t mb, uint32_t cnt){
  asm volatile("mbarrier.init.shared.b64 [%0], %1;" :: "r"(mb), "r"(cnt) : "memory");
}
__device__ __forceinline__ void mbar_wait(uint32_t mb, uint32_t parity){
  uint32_t done;
  asm volatile(
    "{\n\t.reg .pred p;\n\t"
    "mbarrier.try_wait.parity.acquire.cta.shared::cta.b64 p, [%1], %2;\n\t"
    "selp.b32 %0, 1, 0, p;\n\t}"
    : "=r"(done) : "r"(mb), "r"(parity) : "memory");
  if (!done){
    asm volatile(
      "{\n\t.reg .pred P1;\n\t"
      "WL_%=:\n\t"
      "mbarrier.try_wait.parity.acquire.cta.shared::cta.b64 P1, [%0], %1, 0x989680;\n\t"
      "@P1 bra.uni WD_%=;\n\t"
      "bra.uni WL_%=;\n\t"
      "WD_%=:\n\t}"
      :: "r"(mb), "r"(parity) : "memory");
  }
}

__device__ __forceinline__ void ldsm4(uint32_t* r, uint32_t a){
  asm volatile("ldmatrix.sync.aligned.m8n8.x4.shared.b16 {%0,%1,%2,%3},[%4];"
   :"=r"(r[0]),"=r"(r[1]),"=r"(r[2]),"=r"(r[3]):"r"(a));
}
__device__ __forceinline__ void mma16816(float* c, const uint32_t* a, const uint32_t* b){
  asm volatile("mma.sync.aligned.m16n8k16.row.col.f32.bf16.bf16.f32 "
   "{%0,%1,%2,%3},{%4,%5,%6,%7},{%8,%9},{%0,%1,%2,%3};"
   :"+f"(c[0]),"+f"(c[1]),"+f"(c[2]),"+f"(c[3])
   :"r"(a[0]),"r"(a[1]),"r"(a[2]),"r"(a[3]),"r"(b[0]),"r"(b[1]));
}

// ---------------- kernel 1: argmax ----------------
__global__ void k_argmax(const float* __restrict__ y){
  int b = blockIdx.x, t = threadIdx.x;
  __shared__ float vs[256]; __shared__ int is[256];
  vs[t] = y[b*C_ + t]; is[t] = t; __syncthreads();
  for (int s=128; s>0; s>>=1){
    if (t < s){
      float v2 = vs[t+s]; int i2 = is[t+s];
      if (v2 > vs[t] || (v2 == vs[t] && i2 < is[t])) { vs[t]=v2; is[t]=i2; }
    }
    __syncthreads();
  }
  if (t==0) g_idx[b] = is[0];
}

// ---------------- kernel 2: gather leader inputs -> bf16 ----------------
__global__ void k_gather(const float* __restrict__ x_img){
  int b = blockIdx.x, t = threadIdx.x;
  int idx = g_idx[b];
  const float4* src = (const float4*)(x_img + ((size_t)b*C_ + idx)*E_);
  __nv_bfloat162* dst = (__nv_bfloat162*)(g_xl16 + (size_t)b*E_);
  for (int i=t; i<E_/4; i+=256){
    float4 v = src[i];
    dst[i*2+0] = __floats2bfloat162_rn(v.x, v.y);
    dst[i*2+1] = __floats2bfloat162_rn(v.z, v.w);
  }
}

// ---------------- kernel 3: fp32 -> bf16 bulk convert ----------------
__global__ void k_convert(const float* __restrict__ xt, const float* __restrict__ Ww,
                          const float* __restrict__ Wi){
  const long NX4  = (long)B_*Wn_*E_/4;
  const long NW4  = (long)D_*E_/4;
  long i = (long)blockIdx.x*blockDim.x + threadIdx.x;
  long stride = (long)gridDim.x*blockDim.x;
  for (; i < NX4 + 2*NW4; i += stride){
    const float4* src; __nv_bfloat16* dst; long j;
    if (i < NX4)          { src=(const float4*)xt; dst=g_xt16; j=i; }
    else if (i < NX4+NW4) { src=(const float4*)Ww; dst=g_w16;  j=i-NX4; }
    else                  { src=(const float4*)Wi; dst=g_wi16; j=i-NX4-NW4; }
    float4 v = src[j];
    __nv_bfloat162* d2 = (__nv_bfloat162*)(dst + j*4);
    d2[0] = __floats2bfloat162_rn(v.x, v.y);
    d2[1] = __floats2bfloat162_rn(v.z, v.w);
  }
}

// ---------------- kernel 4: leader GEMM, split-K (bf16 mma.sync) ----------------
// grid (16, 8) = (d-tile of 128, k-eighth). M=64, N=128, K=256 per CTA.
__global__ void __launch_bounds__(256) k_leadmma(){
  __shared__ __align__(1024) char sm[49152];
  const int t = threadIdx.x, dt = blockIdx.x, kq = blockIdx.y;
  const int w = t>>5, l = t&31;
  const int wm = w>>2, wn = w&3;
  uint32_t sb = (uint32_t)__cvta_generic_to_shared(sm);

  const __nv_bfloat16* Abase = g_xl16 + (size_t)kq*(E_/KQ_);
  const __nv_bfloat16* Bbase = g_wi16 + (size_t)dt*128*E_ + (size_t)kq*(E_/KQ_);

  float c[2][4][4];
  #pragma unroll
  for (int i=0;i<2;i++) for (int j=0;j<4;j++) for (int e=0;e<4;e++) c[i][j][e]=0.f;

  {
    int u = t; int row=u>>3, seg=u&7;
    cpasync16(sb + 0 + swz(row*128+seg*16), Abase + (size_t)row*E_ + seg*8);
    u = t+256; row=u>>3; seg=u&7;
    cpasync16(sb + 0 + swz(row*128+seg*16), Abase + (size_t)row*E_ + seg*8);
    #pragma unroll
    for (int i=0;i<4;i++){ int v = t+256*i; int r2=v>>3, s2=v&7;
      cpasync16(sb + 16384 + swz(r2*128+s2*16), Bbase + (size_t)r2*E_ + s2*8); }
    cpcommit();
  }
  const uint32_t aRow = (uint32_t)(32*wm + (l&15));
  const uint32_t aSeg = (uint32_t)((l>>4)&1);
  const uint32_t bR4  = (uint32_t)(32*wn + (l&7) + 8*((l>>4)&1));
  const uint32_t bS4  = (uint32_t)((l>>3)&1);

  for (int ks=0; ks<KSL; ks++){
    cpwait0(); __syncthreads();
    if (ks+1 < KSL){
      int p = (ks+1)&1;
      int u=t, row=u>>3, seg=u&7;
      cpasync16(sb + p*8192 + swz(row*128+seg*16), Abase + (size_t)row*E_ + (size_t)(ks+1)*KT + seg*8);
      u=t+256; row=u>>3; seg=u&7;
      cpasync16(sb + p*8192 + swz(row*128+seg*16), Abase + (size_t)row*E_ + (size_t)(ks+1)*KT + seg*8);
      #pragma unroll
      for (int i=0;i<4;i++){ int v=t+256*i; int r2=v>>3, s2=v&7;
        cpasync16(sb + 16384 + p*16384 + swz(r2*128+s2*16),
                  Bbase + (size_t)r2*E_ + (size_t)(ks+1)*KT + s2*8); }
      cpcommit();
    }
    uint32_t ab = sb + (ks&1)*8192;
    uint32_t bb = sb + 16384 + (ks&1)*16384;
    #pragma unroll
    for (int kk=0; kk<KT/16; kk++){
      uint32_t a[2][4], bf4[2][4];
      #pragma unroll
      for (int im=0;im<2;im++)
        ldsm4(a[im], ab + swz((aRow + 16*im)*128 + (kk*16 + aSeg*8)*2));
      #pragma unroll
      for (int pr=0;pr<2;pr++)
        ldsm4(bf4[pr], bb + swz((bR4 + 16*pr)*128 + (kk*16 + bS4*8)*2));
      #pragma unroll
      for (int im=0;im<2;im++)
        #pragma unroll
        for (int pr=0;pr<2;pr++){
          mma16816(c[im][2*pr],   a[im], &bf4[pr][0]);
          mma16816(c[im][2*pr+1], a[im], &bf4[pr][2]);
        }
    }
    __syncthreads();
  }
  float* outp = g_leadp[kq];
  #pragma unroll
  for (int im=0;im<2;im++)
    #pragma unroll
    for (int in_=0;in_<4;in_++)
      #pragma unroll
      for (int e=0;e<4;e++){
        int row = 32*wm + 16*im + (l>>2) + 8*(e>>1);
        int col = 32*wn + 8*in_ + 2*(l&3) + (e&1);
        outp[row*D_ + dt*128 + col] = c[im][in_][e];
      }
}

// ---------------- kernel 4b: merge leader partials + bias ----------------
__global__ void k_leadmerge(const float* __restrict__ bimg){
  int b = blockIdx.x, t = threadIdx.x;
  for (int d = t; d < D_; d += 256){
    int o = b*D_ + d;
    float s = bimg[d];
    #pragma unroll
    for (int q=0;q<KQ_;q++) s += g_leadp[q][o];
    g_leader[o] = s;
  }
}

// ---------------- kernel 5: fused words-GEMM (HMMA, mbarrier pipeline) ----------------
// grid (2, 64, 2) = (wtile, b, d-half). 256 thr, 8 warps as 2(M)x4(N).
// Ring of 3 stages, prefetch depth 2. R6 protocol; empty barriers count-8 with
// per-warp elected arrive (register-neutral).
#define SM_A    0          // 3 x 16384
#define SM_B    49152      // 3 x 16384
#define SM_BIAS 98304      // 128 f
#define SM_LEAD 98816      // 128 f
#define SM_RD   99328      // 512 f
#define SM_RN   101376     // 512 f
#define SM_MBAR 103424     // full[3] @ +0, empty[3] @ +24
#define SMEM_TOTAL 103488

__global__ void __launch_bounds__(256,2) k_main(const float* __restrict__ bwords){
  extern __shared__ __align__(1024) char smem[];
  const int t = threadIdx.x;
  const int wt = blockIdx.x, b = blockIdx.y, dh = blockIdx.z;
  const int w = t>>5, l = t&31;
  const int wm = w>>2, wn = w&3;
  const int gid = l>>2, qid = l&3;
  uint32_t sbase = (uint32_t)__cvta_generic_to_shared(smem);
  float* bias_s = (float*)(smem + SM_BIAS);
  float* lead_s = (float*)(smem + SM_LEAD);
  float* red_d  = (float*)(smem + SM_RD);
  float* red_n  = (float*)(smem + SM_RN);
  const uint32_t mb_full  = sbase + SM_MBAR;
  const uint32_t mb_empty = sbase + SM_MBAR + 24;

  if (t == 0){
    #pragma unroll
    for (int i=0;i<3;i++){ mbar_init(mb_full + i*8, 256); mbar_init(mb_empty + i*8, 8); }
  }
  __syncthreads();

  const __nv_bfloat16* Abase  = g_xt16 + ((size_t)(b*Wn_ + wt*128))*E_;
  const __nv_bfloat16* Bbase0 = g_w16 + (size_t)(dh*NCHP)*128*E_;

  // per-thread fixed load offsets (4 chunks A + 4 chunks B per stage)
  uint32_t aSm[4]; uint32_t gOff[4];
  #pragma unroll
  for (int i=0;i<4;i++){
    int u = t + 256*i; int row = u>>3, seg = u&7;
    aSm[i]  = sbase + SM_A + swz((uint32_t)(row*128 + seg*16));
    gOff[i] = (uint32_t)(row*E_ + seg*8);
  }

  // prologue: produce stages 0,1 (fresh empty barriers, no wait needed)
  #pragma unroll
  for (int gp=0; gp<2; gp++){
    const __nv_bfloat16* Ap = Abase  + gp*KT;
    const __nv_bfloat16* Bp = Bbase0 + gp*KT;
    #pragma unroll
    for (int i=0;i<4;i++) cpasync16(aSm[i] + (uint32_t)(gp*16384), Ap + gOff[i]);
    #pragma unroll
    for (int i=0;i<4;i++) cpasync16(aSm[i] + (uint32_t)(49152 + gp*16384), Bp + gOff[i]);
    cp_mbar_arrive(mb_full + gp*8);
  }

  const uint32_t aRow = (uint32_t)(64*wm + (l&15));
  const uint32_t aSeg = (uint32_t)((l>>4)&1);
  const uint32_t bR4  = (uint32_t)(32*wn + (l&7) + 8*((l>>4)&1));
  const uint32_t bS4  = (uint32_t)((l>>3)&1);

  float dot_tot = 0.f, nrm_tot = 0.f;
  float c[4][4][4];

  int sP = 2, pPw = 1;   // produce cursor (slot, parity-to-wait on empty)
  int sC = 0, pC = 0;    // consume cursor (slot, parity-to-wait on full)

  for (int nc=0; nc<NCHP; nc++){
    #pragma unroll
    for (int i=0;i<4;i++)
      #pragma unroll
      for (int j=0;j<4;j++)
        #pragma unroll
        for (int e=0;e<4;e++) c[i][j][e]=0.f;

    for (int ks=0; ks<KSTEPS; ks++){
      const int gs = nc*KSTEPS + ks;
      // produce stage gs+2 (requires warps consumed stage gs-1 -> 1 stage skew slack)
      if (gs+2 < NCHP*KSTEPS){
        mbar_wait(mb_empty + sP*8, (uint32_t)pPw);
        const int gp = gs+2, ksP = gp & (KSTEPS-1), ncP = gp >> 5;
        const __nv_bfloat16* Ap = Abase  + ksP*KT;
        const __nv_bfloat16* Bp = Bbase0 + (size_t)(ncP*128)*E_ + ksP*KT;
        const uint32_t so = (uint32_t)(sP*16384);
        #pragma unroll
        for (int i=0;i<4;i++) cpasync16(aSm[i] + so, Ap + gOff[i]);
        #pragma unroll
        for (int i=0;i<4;i++) cpasync16(aSm[i] + 49152u + so, Bp + gOff[i]);
        cp_mbar_arrive(mb_full + sP*8);
        if (++sP == 3){ sP = 0; pPw ^= 1; }
      }
      // consume stage gs
      mbar_wait(mb_full + sC*8, (uint32_t)pC);
      {
        uint32_t abuf = sbase + SM_A + (uint32_t)(sC*16384);
        uint32_t bbuf = sbase + SM_B + (uint32_t)(sC*16384);
        #pragma unroll
        for (int kk=0; kk<KT/16; kk++){
          uint32_t a[4][4], bf4[2][4];
          #pragma unroll
          for (int im=0;im<4;im++)
            ldsm4(a[im], abuf + swz((aRow + 16*im)*128 + (kk*16 + aSeg*8)*2));
          #pragma unroll
          for (int pr=0;pr<2;pr++)
            ldsm4(bf4[pr], bbuf + swz((bR4 + 16*pr)*128 + (kk*16 + bS4*8)*2));
          #pragma unroll
          for (int im=0;im<4;im++)
            #pragma unroll
            for (int pr=0;pr<2;pr++){
              mma16816(c[im][2*pr],   a[im], &bf4[pr][0]);
              mma16816(c[im][2*pr+1], a[im], &bf4[pr][2]);
            }
        }
      }
      __syncwarp();
      if (l == 0) mbar_arrive(mb_empty + sC*8);
      if (++sC == 3){ sC = 0; pC ^= 1; }
    }

    // ---- epilogue for this n-chunk ----
    const int ncg = dh*NCHP + nc;
    __syncthreads();
    if (t < 128){
      bias_s[t] = bwords[ncg*128 + t];
      lead_s[t] = g_leader[b*D_ + ncg*128 + t];
    }
    __syncthreads();
    float dp[8], np2[8];
    #pragma unroll
    for (int s=0;s<8;s++){ dp[s]=0.f; np2[s]=0.f; }
    #pragma unroll
    for (int im=0;im<4;im++)
      #pragma unroll
      for (int in_=0;in_<4;in_++)
        #pragma unroll
        for (int e=0;e<4;e++){
          int col = 32*wn + 8*in_ + 2*qid + (e&1);
          float v = c[im][in_][e] + bias_s[col];
          int s = im*2 + (e>>1);
          dp[s]  += v * lead_s[col];
          np2[s] += v * v;
        }
    #pragma unroll
    for (int s=0;s<8;s++){
      dp[s]  += __shfl_xor_sync(0xffffffffu, dp[s], 1);
      dp[s]  += __shfl_xor_sync(0xffffffffu, dp[s], 2);
      np2[s] += __shfl_xor_sync(0xffffffffu, np2[s], 1);
      np2[s] += __shfl_xor_sync(0xffffffffu, np2[s], 2);
    }
    if (qid == 0){
      #pragma unroll
      for (int s=0;s<8;s++){
        int r = 64*wm + 16*(s>>1) + gid + 8*(s&1);
        red_d[wn*128 + r] = dp[s];
        red_n[wn*128 + r] = np2[s];
      }
    }
    __syncthreads();
    if (t < 128){
      float ds=0.f, ns=0.f;
      #pragma unroll
      for (int q=0;q<4;q++){ ds += red_d[q*128+t]; ns += red_n[q*128+t]; }
      dot_tot += ds; nrm_tot += ns;
    }
    __syncthreads();
  }

  if (t < 128){
    int o = b*Wn_ + wt*128 + t;
    g_dotp[dh][o] = dot_tot;
    g_nrmp[dh][o] = nrm_tot;
  }
}

// ---------------- kernel 6: cosine + softmax ----------------
__global__ void k_final(float* __restrict__ out){
  int b = blockIdx.x, t = threadIdx.x;
  __shared__ float sh[256];
  float s = 0.f;
  const float* lr = g_leader + b*D_;
  for (int i=t; i<D_; i+=256){ float v = lr[i]; s += v*v; }
  sh[t] = s; __syncthreads();
  for (int st=128; st>0; st>>=1){ if (t<st) sh[t]+=sh[t+st]; __syncthreads(); }
  float ln = sqrtf(sh[0]);
  __syncthreads();

  int o = b*Wn_ + t;
  float dot = g_dotp[0][o] + g_dotp[1][o];
  float nr  = sqrtf(g_nrmp[0][o] + g_nrmp[1][o]);
  float logit = dot / fmaxf(ln*nr, 1e-8f);

  sh[t] = logit; __syncthreads();
  for (int st=128; st>0; st>>=1){ if (t<st) sh[t]=fmaxf(sh[t],sh[t+st]); __syncthreads(); }
  float mx = sh[0]; __syncthreads();
  float ex = expf(logit - mx);
  sh[t] = ex; __syncthreads();
  for (int st=128; st>0; st>>=1){ if (t<st) sh[t]+=sh[t+st]; __syncthreads(); }
  out[b*Wn_ + t] = ex / sh[0];
}

// ---------------- launcher ----------------
extern "C" void kernel_launch(void* const* d_in, const int* in_sizes, int n_in,
                              void* d_out, int out_size){
  const float* x_img = (const float*)d_in[0];
  const float* x_txt = (const float*)d_in[1];
  const float* y     = (const float*)d_in[2];
  const float* Wimg  = (const float*)d_in[3];
  const float* bimg  = (const float*)d_in[4];
  const float* Ww    = (const float*)d_in[5];
  const float* bw    = (const float*)d_in[6];
  float* out = (float*)d_out;

  cudaFuncSetAttribute(k_main, cudaFuncAttributeMaxDynamicSharedMemorySize, SMEM_TOTAL);

  k_argmax<<<B_, 256>>>(y);
  k_gather<<<B_, 256>>>(x_img);
  k_convert<<<2048, 256>>>(x_txt, Ww, Wimg);
  k_leadmma<<<dim3(D_/128, KQ_), 256>>>();
  k_leadmerge<<<B_, 256>>>(bimg);
  k_main<<<dim3(2, B_, 2), 256, SMEM_TOTAL>>>(bw);
  k_final<<<B_, 256>>>(out);
}

// round 14
// speedup vs baseline: 1.4334x; 1.0096x over previous
#include <cuda_runtime.h>
#include <cuda_bf16.h>
#include <cstdint>

#define B_  64
#define C_  256
#define Wn_ 256
#define E_  2048
#define D_  2048

#define KT     64            // bf16 K per stage (128B rows, SW128)
#define KSTEPS (E_/KT)       // 32
#define NCHP   8             // n-chunks (of 128 cols) per CTA; 2 CTAs cover D
#define KQ_    8             // leader GEMM K-splits
#define KSL    (E_/KQ_/KT)   // 4 k-steps per leader CTA

// ---------------- scratch ----------------
__device__ int   g_idx[B_];
__device__ float g_leader[B_*D_];
__device__ float g_leadp[KQ_][B_*D_];
__device__ float g_dotp[2][B_*Wn_];
__device__ float g_nrmp[2][B_*Wn_];
__device__ __nv_bfloat16 g_xt16[(size_t)B_*Wn_*E_];   // 64 MB
__device__ __nv_bfloat16 g_w16[(size_t)D_*E_];        //  8 MB
__device__ __nv_bfloat16 g_wi16[(size_t)D_*E_];       //  8 MB
__device__ __nv_bfloat16 g_xl16[(size_t)B_*E_];       // 256 KB

// ---------------- helpers ----------------
__device__ __forceinline__ uint32_t swz(uint32_t o){ return o ^ ((o>>3)&0x70); }

__device__ __forceinline__ void cpasync16(uint32_t s, const void* g){
  asm volatile("cp.async.cg.shared.global [%0],[%1],16;"::"r"(s),"l"(g));
}
__device__ __forceinline__ void cpcommit(){ asm volatile("cp.async.commit_group;"); }
__device__ __forceinline__ void cpwait0(){ asm volatile("cp.async.wait_group 0;"); }

__device__ __forceinline__ void cp_mbar_arrive(uint32_t mb){
  asm volatile("cp.async.mbarrier.arrive.noinc.shared.b64 [%0];" :: "r"(mb) : "memory");
}
__device__ __forceinline__ void mbar_arrive(uint32_t mb){
  asm volatile("mbarrier.arrive.shared.b64 _, [%0];" :: "r"(mb) : "memory");
}
__device__ __forceinline__ void mbar_init(uint32_t mb, uint32_t cnt){
  asm volatile("mbarrier.init.shared.b64 [%0], %1;" :: "r"(mb), "r"(cnt) : "memory");
}
__device__ __forceinline__ void mbar_wait(uint32_t mb, uint32_t parity){
  uint32_t done;
  asm volatile(
    "{\n\t.reg .pred p;\n\t"
    "mbarrier.try_wait.parity.acquire.cta.shared::cta.b64 p, [%1], %2;\n\t"
    "selp.b32 %0, 1, 0, p;\n\t}"
    : "=r"(done) : "r"(mb), "r"(parity) : "memory");
  if (!done){
    asm volatile(
      "{\n\t.reg .pred P1;\n\t"
      "WL_%=:\n\t"
      "mbarrier.try_wait.parity.acquire.cta.shared::cta.b64 P1, [%0], %1, 0x989680;\n\t"
      "@P1 bra.uni WD_%=;\n\t"
      "bra.uni WL_%=;\n\t"
      "WD_%=:\n\t}"
      :: "r"(mb), "r"(parity) : "memory");
  }
}

__device__ __forceinline__ void ldsm4(uint32_t* r, uint32_t a){
  asm volatile("ldmatrix.sync.aligned.m8n8.x4.shared.b16 {%0,%1,%2,%3},[%4];"
   :"=r"(r[0]),"=r"(r[1]),"=r"(r[2]),"=r"(r[3]):"r"(a));
}
__device__ __forceinline__ void mma16816(float* c, const uint32_t* a, const uint32_t* b){
  asm volatile("mma.sync.aligned.m16n8k16.row.col.f32.bf16.bf16.f32 "
   "{%0,%1,%2,%3},{%4,%5,%6,%7},{%8,%9},{%0,%1,%2,%3};"
   :"+f"(c[0]),"+f"(c[1]),"+f"(c[2]),"+f"(c[3])
   :"r"(a[0]),"r"(a[1]),"r"(a[2]),"r"(a[3]),"r"(b[0]),"r"(b[1]));
}

// ---------------- kernel 1: argmax + gather leader row -> bf16 ----------------
__global__ void k_argmax_gather(const float* __restrict__ y,
                                const float* __restrict__ x_img){
  int b = blockIdx.x, t = threadIdx.x;
  __shared__ float vs[256]; __shared__ int is[256];
  vs[t] = y[b*C_ + t]; is[t] = t; __syncthreads();
  for (int s=128; s>0; s>>=1){
    if (t < s){
      float v2 = vs[t+s]; int i2 = is[t+s];
      if (v2 > vs[t] || (v2 == vs[t] && i2 < is[t])) { vs[t]=v2; is[t]=i2; }
    }
    __syncthreads();
  }
  if (t==0) g_idx[b] = is[0];
  __syncthreads();
  int idx = is[0];
  const float4* src = (const float4*)(x_img + ((size_t)b*C_ + idx)*E_);
  __nv_bfloat162* dst = (__nv_bfloat162*)(g_xl16 + (size_t)b*E_);
  for (int i=t; i<E_/4; i+=256){
    float4 v = src[i];
    dst[i*2+0] = __floats2bfloat162_rn(v.x, v.y);
    dst[i*2+1] = __floats2bfloat162_rn(v.z, v.w);
  }
}

// ---------------- kernel 3: fp32 -> bf16 bulk convert ----------------
__global__ void k_convert(const float* __restrict__ xt, const float* __restrict__ Ww,
                          const float* __restrict__ Wi){
  const long NX4  = (long)B_*Wn_*E_/4;
  const long NW4  = (long)D_*E_/4;
  long i = (long)blockIdx.x*blockDim.x + threadIdx.x;
  long stride = (long)gridDim.x*blockDim.x;
  for (; i < NX4 + 2*NW4; i += stride){
    const float4* src; __nv_bfloat16* dst; long j;
    if (i < NX4)          { src=(const float4*)xt; dst=g_xt16; j=i; }
    else if (i < NX4+NW4) { src=(const float4*)Ww; dst=g_w16;  j=i-NX4; }
    else                  { src=(const float4*)Wi; dst=g_wi16; j=i-NX4-NW4; }
    float4 v = src[j];
    __nv_bfloat162* d2 = (__nv_bfloat162*)(dst + j*4);
    d2[0] = __floats2bfloat162_rn(v.x, v.y);
    d2[1] = __floats2bfloat162_rn(v.z, v.w);
  }
}

// ---------------- kernel 4: leader GEMM, split-K (bf16 mma.sync) ----------------
// grid (16, 8) = (d-tile of 128, k-eighth). M=64, N=128, K=256 per CTA.
__global__ void __launch_bounds__(256) k_leadmma(){
  __shared__ __align__(1024) char sm[49152];
  const int t = threadIdx.x, dt = blockIdx.x, kq = blockIdx.y;
  const int w = t>>5, l = t&31;
  const int wm = w>>2, wn = w&3;
  uint32_t sb = (uint32_t)__cvta_generic_to_shared(sm);

  const __nv_bfloat16* Abase = g_xl16 + (size_t)kq*(E_/KQ_);
  const __nv_bfloat16* Bbase = g_wi16 + (size_t)dt*128*E_ + (size_t)kq*(E_/KQ_);

  float c[2][4][4];
  #pragma unroll
  for (int i=0;i<2;i++) for (int j=0;j<4;j++) for (int e=0;e<4;e++) c[i][j][e]=0.f;

  {
    int u = t; int row=u>>3, seg=u&7;
    cpasync16(sb + 0 + swz(row*128+seg*16), Abase + (size_t)row*E_ + seg*8);
    u = t+256; row=u>>3; seg=u&7;
    cpasync16(sb + 0 + swz(row*128+seg*16), Abase + (size_t)row*E_ + seg*8);
    #pragma unroll
    for (int i=0;i<4;i++){ int v = t+256*i; int r2=v>>3, s2=v&7;
      cpasync16(sb + 16384 + swz(r2*128+s2*16), Bbase + (size_t)r2*E_ + s2*8); }
    cpcommit();
  }
  const uint32_t aRow = (uint32_t)(32*wm + (l&15));
  const uint32_t aSeg = (uint32_t)((l>>4)&1);
  const uint32_t bR4  = (uint32_t)(32*wn + (l&7) + 8*((l>>4)&1));
  const uint32_t bS4  = (uint32_t)((l>>3)&1);

  for (int ks=0; ks<KSL; ks++){
    cpwait0(); __syncthreads();
    if (ks+1 < KSL){
      int p = (ks+1)&1;
      int u=t, row=u>>3, seg=u&7;
      cpasync16(sb + p*8192 + swz(row*128+seg*16), Abase + (size_t)row*E_ + (size_t)(ks+1)*KT + seg*8);
      u=t+256; row=u>>3; seg=u&7;
      cpasync16(sb + p*8192 + swz(row*128+seg*16), Abase + (size_t)row*E_ + (size_t)(ks+1)*KT + seg*8);
      #pragma unroll
      for (int i=0;i<4;i++){ int v=t+256*i; int r2=v>>3, s2=v&7;
        cpasync16(sb + 16384 + p*16384 + swz(r2*128+s2*16),
                  Bbase + (size_t)r2*E_ + (size_t)(ks+1)*KT + s2*8); }
      cpcommit();
    }
    uint32_t ab = sb + (ks&1)*8192;
    uint32_t bb = sb + 16384 + (ks&1)*16384;
    #pragma unroll
    for (int kk=0; kk<KT/16; kk++){
      uint32_t a[2][4], bf4[2][4];
      #pragma unroll
      for (int im=0;im<2;im++)
        ldsm4(a[im], ab + swz((aRow + 16*im)*128 + (kk*16 + aSeg*8)*2));
      #pragma unroll
      for (int pr=0;pr<2;pr++)
        ldsm4(bf4[pr], bb + swz((bR4 + 16*pr)*128 + (kk*16 + bS4*8)*2));
      #pragma unroll
      for (int im=0;im<2;im++)
        #pragma unroll
        for (int pr=0;pr<2;pr++){
          mma16816(c[im][2*pr],   a[im], &bf4[pr][0]);
          mma16816(c[im][2*pr+1], a[im], &bf4[pr][2]);
        }
    }
    __syncthreads();
  }
  float* outp = g_leadp[kq];
  #pragma unroll
  for (int im=0;im<2;im++)
    #pragma unroll
    for (int in_=0;in_<4;in_++)
      #pragma unroll
      for (int e=0;e<4;e++){
        int row = 32*wm + 16*im + (l>>2) + 8*(e>>1);
        int col = 32*wn + 8*in_ + 2*(l&3) + (e&1);
        outp[row*D_ + dt*128 + col] = c[im][in_][e];
      }
}

// ---------------- kernel 4b: merge leader partials + bias ----------------
__global__ void k_leadmerge(const float* __restrict__ bimg){
  int b = blockIdx.x, t = threadIdx.x;
  for (int d = t; d < D_; d += 256){
    int o = b*D_ + d;
    float s = bimg[d];
    #pragma unroll
    for (int q=0;q<KQ_;q++) s += g_leadp[q][o];
    g_leader[o] = s;
  }
}

// ---------------- kernel 5: fused words-GEMM (HMMA, mbarrier pipeline) ----------------
// grid (2, 64, 2) = (wtile, b, d-half). 256 thr, 8 warps as 2(M)x4(N).
// Ring of 3 stages, prefetch depth 2. CONSUME-FIRST ordering: the full-wait
// (cp.async completion) gates the MMAs; the inter-warp empty rendezvous happens
// after the MMA burst, where there is a full k-step of slack.
#define SM_A    0          // 3 x 16384
#define SM_B    49152      // 3 x 16384
#define SM_BIAS 98304      // 128 f
#define SM_LEAD 98816      // 128 f
#define SM_RD   99328      // 512 f
#define SM_RN   101376     // 512 f
#define SM_MBAR 103424     // full[3] @ +0, empty[3] @ +24
#define SMEM_TOTAL 103488

__global__ void __launch_bounds__(256,2) k_main(const float* __restrict__ bwords){
  extern __shared__ __align__(1024) char smem[];
  const int t = threadIdx.x;
  const int wt = blockIdx.x, b = blockIdx.y, dh = blockIdx.z;
  const int w = t>>5, l = t&31;
  const int wm = w>>2, wn = w&3;
  const int gid = l>>2, qid = l&3;
  uint32_t sbase = (uint32_t)__cvta_generic_to_shared(smem);
  float* bias_s = (float*)(smem + SM_BIAS);
  float* lead_s = (float*)(smem + SM_LEAD);
  float* red_d  = (float*)(smem + SM_RD);
  float* red_n  = (float*)(smem + SM_RN);
  const uint32_t mb_full  = sbase + SM_MBAR;
  const uint32_t mb_empty = sbase + SM_MBAR + 24;

  if (t == 0){
    #pragma unroll
    for (int i=0;i<3;i++){ mbar_init(mb_full + i*8, 256); mbar_init(mb_empty + i*8, 8); }
  }
  __syncthreads();

  const __nv_bfloat16* Abase  = g_xt16 + ((size_t)(b*Wn_ + wt*128))*E_;
  const __nv_bfloat16* Bbase0 = g_w16 + (size_t)(dh*NCHP)*128*E_;

  // per-thread fixed load offsets (4 chunks A + 4 chunks B per stage)
  uint32_t aSm[4]; uint32_t gOff[4];
  #pragma unroll
  for (int i=0;i<4;i++){
    int u = t + 256*i; int row = u>>3, seg = u&7;
    aSm[i]  = sbase + SM_A + swz((uint32_t)(row*128 + seg*16));
    gOff[i] = (uint32_t)(row*E_ + seg*8);
  }

  // prologue: produce stages 0,1 (fresh empty barriers, no wait needed)
  #pragma unroll
  for (int gp=0; gp<2; gp++){
    const __nv_bfloat16* Ap = Abase  + gp*KT;
    const __nv_bfloat16* Bp = Bbase0 + gp*KT;
    #pragma unroll
    for (int i=0;i<4;i++) cpasync16(aSm[i] + (uint32_t)(gp*16384), Ap + gOff[i]);
    #pragma unroll
    for (int i=0;i<4;i++) cpasync16(aSm[i] + (uint32_t)(49152 + gp*16384), Bp + gOff[i]);
    cp_mbar_arrive(mb_full + gp*8);
  }

  const uint32_t aRow = (uint32_t)(64*wm + (l&15));
  const uint32_t aSeg = (uint32_t)((l>>4)&1);
  const uint32_t bR4  = (uint32_t)(32*wn + (l&7) + 8*((l>>4)&1));
  const uint32_t bS4  = (uint32_t)((l>>3)&1);

  float dot_tot = 0.f, nrm_tot = 0.f;
  float c[4][4][4];

  int sP = 2, pPw = 1;   // produce cursor (slot, parity-to-wait on empty)
  int sC = 0, pC = 0;    // consume cursor (slot, parity-to-wait on full)

  for (int nc=0; nc<NCHP; nc++){
    #pragma unroll
    for (int i=0;i<4;i++)
      #pragma unroll
      for (int j=0;j<4;j++)
        #pragma unroll
        for (int e=0;e<4;e++) c[i][j][e]=0.f;

    for (int ks=0; ks<KSTEPS; ks++){
      const int gs = nc*KSTEPS + ks;
      // ---- consume stage gs FIRST (gated only by cp.async completion) ----
      mbar_wait(mb_full + sC*8, (uint32_t)pC);
      {
        uint32_t abuf = sbase + SM_A + (uint32_t)(sC*16384);
        uint32_t bbuf = sbase + SM_B + (uint32_t)(sC*16384);
        #pragma unroll
        for (int kk=0; kk<KT/16; kk++){
          uint32_t a[4][4], bf4[2][4];
          #pragma unroll
          for (int im=0;im<4;im++)
            ldsm4(a[im], abuf + swz((aRow + 16*im)*128 + (kk*16 + aSeg*8)*2));
          #pragma unroll
          for (int pr=0;pr<2;pr++)
            ldsm4(bf4[pr], bbuf + swz((bR4 + 16*pr)*128 + (kk*16 + bS4*8)*2));
          #pragma unroll
          for (int im=0;im<4;im++)
            #pragma unroll
            for (int pr=0;pr<2;pr++){
              mma16816(c[im][2*pr],   a[im], &bf4[pr][0]);
              mma16816(c[im][2*pr+1], a[im], &bf4[pr][2]);
            }
        }
      }
      __syncwarp();
      if (l == 0) mbar_arrive(mb_empty + sC*8);
      if (++sC == 3){ sC = 0; pC ^= 1; }

      // ---- then produce stage gs+2 (inter-warp rendezvous has full-k-step slack) ----
      if (gs+2 < NCHP*KSTEPS){
        mbar_wait(mb_empty + sP*8, (uint32_t)pPw);
        const int gp = gs+2, ksP = gp & (KSTEPS-1), ncP = gp >> 5;
        const __nv_bfloat16* Ap = Abase  + ksP*KT;
        const __nv_bfloat16* Bp = Bbase0 + (size_t)(ncP*128)*E_ + ksP*KT;
        const uint32_t so = (uint32_t)(sP*16384);
        #pragma unroll
        for (int i=0;i<4;i++) cpasync16(aSm[i] + so, Ap + gOff[i]);
        #pragma unroll
        for (int i=0;i<4;i++) cpasync16(aSm[i] + 49152u + so, Bp + gOff[i]);
        cp_mbar_arrive(mb_full + sP*8);
        if (++sP == 3){ sP = 0; pPw ^= 1; }
      }
    }

    // ---- epilogue for this n-chunk ----
    const int ncg = dh*NCHP + nc;
    __syncthreads();
    if (t < 128){
      bias_s[t] = bwords[ncg*128 + t];
      lead_s[t] = g_leader[b*D_ + ncg*128 + t];
    }
    __syncthreads();
    float dp[8], np2[8];
    #pragma unroll
    for (int s=0;s<8;s++){ dp[s]=0.f; np2[s]=0.f; }
    #pragma unroll
    for (int im=0;im<4;im++)
      #pragma unroll
      for (int in_=0;in_<4;in_++)
        #pragma unroll
        for (int e=0;e<4;e++){
          int col = 32*wn + 8*in_ + 2*qid + (e&1);
          float v = c[im][in_][e] + bias_s[col];
          int s = im*2 + (e>>1);
          dp[s]  += v * lead_s[col];
          np2[s] += v * v;
        }
    #pragma unroll
    for (int s=0;s<8;s++){
      dp[s]  += __shfl_xor_sync(0xffffffffu, dp[s], 1);
      dp[s]  += __shfl_xor_sync(0xffffffffu, dp[s], 2);
      np2[s] += __shfl_xor_sync(0xffffffffu, np2[s], 1);
      np2[s] += __shfl_xor_sync(0xffffffffu, np2[s], 2);
    }
    if (qid == 0){
      #pragma unroll
      for (int s=0;s<8;s++){
        int r = 64*wm + 16*(s>>1) + gid + 8*(s&1);
        red_d[wn*128 + r] = dp[s];
        red_n[wn*128 + r] = np2[s];
      }
    }
    __syncthreads();
    if (t < 128){
      float ds=0.f, ns=0.f;
      #pragma unroll
      for (int q=0;q<4;q++){ ds += red_d[q*128+t]; ns += red_n[q*128+t]; }
      dot_tot += ds; nrm_tot += ns;
    }
    __syncthreads();
  }

  if (t < 128){
    int o = b*Wn_ + wt*128 + t;
    g_dotp[dh][o] = dot_tot;
    g_nrmp[dh][o] = nrm_tot;
  }
}

// ---------------- kernel 6: cosine + softmax ----------------
__global__ void k_final(float* __restrict__ out){
  int b = blockIdx.x, t = threadIdx.x;
  __shared__ float sh[256];
  float s = 0.f;
  const float* lr = g_leader + b*D_;
  for (int i=t; i<D_; i+=256){ float v = lr[i]; s += v*v; }
  sh[t] = s; __syncthreads();
  for (int st=128; st>0; st>>=1){ if (t<st) sh[t]+=sh[t+st]; __syncthreads(); }
  float ln = sqrtf(sh[0]);
  __syncthreads();

  int o = b*Wn_ + t;
  float dot = g_dotp[0][o] + g_dotp[1][o];
  float nr  = sqrtf(g_nrmp[0][o] + g_nrmp[1][o]);
  float logit = dot / fmaxf(ln*nr, 1e-8f);

  sh[t] = logit; __syncthreads();
  for (int st=128; st>0; st>>=1){ if (t<st) sh[t]=fmaxf(sh[t],sh[t+st]); __syncthreads(); }
  float mx = sh[0]; __syncthreads();
  float ex = expf(logit - mx);
  sh[t] = ex; __syncthreads();
  for (int st=128; st>0; st>>=1){ if (t<st) sh[t]+=sh[t+st]; __syncthreads(); }
  out[b*Wn_ + t] = ex / sh[0];
}

// ---------------- launcher ----------------
extern "C" void kernel_launch(void* const* d_in, const int* in_sizes, int n_in,
                              void* d_out, int out_size){
  const float* x_img = (const float*)d_in[0];
  const float* x_txt = (const float*)d_in[1];
  const float* y     = (const float*)d_in[2];
  const float* Wimg  = (const float*)d_in[3];
  const float* bimg  = (const float*)d_in[4];
  const float* Ww    = (const float*)d_in[5];
  const float* bw    = (const float*)d_in[6];
  float* out = (float*)d_out;

  cudaFuncSetAttribute(k_main, cudaFuncAttributeMaxDynamicSharedMemorySize, SMEM_TOTAL);

  k_argmax_gather<<<B_, 256>>>(y, x_img);
  k_convert<<<2048, 256>>>(x_txt, Ww, Wimg);
  k_leadmma<<<dim3(D_/128, KQ_), 256>>>();
  k_leadmerge<<<B_, 256>>>(bimg);
  k_main<<<dim3(2, B_, 2), 256, SMEM_TOTAL>>>(bw);
  k_final<<<B_, 256>>>(out);
}